// round 1
// baseline (speedup 1.0000x reference)
#include <cuda_runtime.h>
#include <cuda_bf16.h>
#include <math.h>

// ---------------------------------------------------------------------------
// AliNetGraphAttentionLayer: BN -> 3 fused GEMMs -> quadratic-form scores ->
// edge leaky-relu + row softmax -> SpMM.
// Shapes: N=100000 nodes, D_IN=256, D_OUT=128, E=1600000 edges (rows sorted).
// ---------------------------------------------------------------------------

#define D_IN   256
#define D_OUT  128
#define NMAX   100096
#define EPS    1e-3f
#define LEAKY  0.2f
#define NB_BN  400      // partial-reduction blocks for BN stats

// ---- scratch (device globals: allocation-free rule) -----------------------
__device__ float g_psum[NB_BN * D_IN];
__device__ float g_psq [NB_BN * D_IN];
__device__ float g_mean[D_IN];
__device__ float g_rstd[D_IN];
__device__ float g_s1[NMAX];
__device__ float g_s2[NMAX];
__device__ float g_mapped[(size_t)NMAX * D_OUT];   // xn @ w      [N,128]
__device__ float g_y[(size_t)NMAX * 512];          // [xn@w1 | xn@w2] [N,512]

// ---------------------------------------------------------------------------
// K1a: per-block partial column sums / sumsq
// ---------------------------------------------------------------------------
__global__ __launch_bounds__(256) void bn_partial(const float* __restrict__ x, int n) {
    int col = threadIdx.x;                    // 0..255
    int per = (n + gridDim.x - 1) / gridDim.x;
    int r0 = blockIdx.x * per;
    int r1 = min(n, r0 + per);
    float s = 0.f, q = 0.f;
    for (int r = r0; r < r1; ++r) {
        float v = x[(size_t)r * D_IN + col];
        s += v;
        q += v * v;
    }
    g_psum[blockIdx.x * D_IN + col] = s;
    g_psq [blockIdx.x * D_IN + col] = q;
}

// ---------------------------------------------------------------------------
// K1b: finalize mean / rstd (deterministic single-block reduce)
// ---------------------------------------------------------------------------
__global__ __launch_bounds__(256) void bn_finalize(int n, int nb) {
    int col = threadIdx.x;
    float s = 0.f, q = 0.f;
    for (int b = 0; b < nb; ++b) {
        s += g_psum[b * D_IN + col];
        q += g_psq [b * D_IN + col];
    }
    float mean = s / (float)n;
    float var  = q / (float)n - mean * mean;
    g_mean[col] = mean;
    g_rstd[col] = rsqrtf(var + EPS);
}

// ---------------------------------------------------------------------------
// K2: fused BN-normalize + GEMM  C[N,640] = xn @ [w | w1 | w2]
//     BM=128, BN=64, BK=32, 256 threads, 8x4 per-thread tile.
//     Epilogue routes cols [0,128) -> g_mapped, [128,640) -> g_y.
// ---------------------------------------------------------------------------
__global__ __launch_bounds__(256) void gemm_fused(
    const float* __restrict__ x,
    const float* __restrict__ w,
    const float* __restrict__ w1,
    const float* __restrict__ w2,
    int n)
{
    __shared__ float As[32][132];   // [k][m], padded
    __shared__ float Bs[32][68];    // [k][c], padded

    const int tid = threadIdx.x;
    const int tx  = tid & 15;       // 0..15 -> 4 cols each
    const int ty  = tid >> 4;       // 0..15 -> 8 rows each

    const int colBase = blockIdx.x * 64;    // 0..576
    const int rowBase = blockIdx.y * 128;

    // select source weight matrix for this 64-col stripe
    const float* Bsrc;
    int ldb, srcCol;
    if (colBase < 128)       { Bsrc = w;  ldb = 128; srcCol = colBase; }
    else if (colBase < 384)  { Bsrc = w1; ldb = 256; srcCol = colBase - 128; }
    else                     { Bsrc = w2; ldb = 256; srcCol = colBase - 384; }

    float acc[8][4];
    #pragma unroll
    for (int r = 0; r < 8; ++r)
        #pragma unroll
        for (int c = 0; c < 4; ++c) acc[r][c] = 0.f;

    for (int kBase = 0; kBase < D_IN; kBase += 32) {
        // --- load A tile (128 rows x 32 k), BN applied, stored transposed ---
        {
            int k4 = (tid & 7) * 4;                 // 0,4,..,28
            float4 mn = *(const float4*)&g_mean[kBase + k4];
            float4 rs = *(const float4*)&g_rstd[kBase + k4];
            #pragma unroll
            for (int p = 0; p < 4; ++p) {
                int rl = (tid >> 3) + p * 32;       // 0..127
                int row = rowBase + rl;
                float4 v;
                if (row < n) v = *(const float4*)&x[(size_t)row * D_IN + kBase + k4];
                else         v = make_float4(0.f, 0.f, 0.f, 0.f);
                As[k4 + 0][rl] = (v.x - mn.x) * rs.x;
                As[k4 + 1][rl] = (v.y - mn.y) * rs.y;
                As[k4 + 2][rl] = (v.z - mn.z) * rs.z;
                As[k4 + 3][rl] = (v.w - mn.w) * rs.w;
            }
        }
        // --- load B tile (32 k x 64 cols) ---
        {
            int c4 = (tid & 15) * 4;
            #pragma unroll
            for (int p = 0; p < 2; ++p) {
                int kk = (tid >> 4) + p * 16;
                float4 v = *(const float4*)&Bsrc[(size_t)(kBase + kk) * ldb + srcCol + c4];
                Bs[kk][c4 + 0] = v.x;
                Bs[kk][c4 + 1] = v.y;
                Bs[kk][c4 + 2] = v.z;
                Bs[kk][c4 + 3] = v.w;
            }
        }
        __syncthreads();

        #pragma unroll
        for (int kk = 0; kk < 32; ++kk) {
            float a[8], b[4];
            float4 a0 = *(const float4*)&As[kk][ty * 8];
            float4 a1 = *(const float4*)&As[kk][ty * 8 + 4];
            a[0]=a0.x; a[1]=a0.y; a[2]=a0.z; a[3]=a0.w;
            a[4]=a1.x; a[5]=a1.y; a[6]=a1.z; a[7]=a1.w;
            float4 b0 = *(const float4*)&Bs[kk][tx * 4];
            b[0]=b0.x; b[1]=b0.y; b[2]=b0.z; b[3]=b0.w;
            #pragma unroll
            for (int r = 0; r < 8; ++r)
                #pragma unroll
                for (int c = 0; c < 4; ++c)
                    acc[r][c] = fmaf(a[r], b[c], acc[r][c]);
        }
        __syncthreads();
    }

    // --- epilogue: route to mapped / y ---
    int gcol = colBase + tx * 4;
    #pragma unroll
    for (int r = 0; r < 8; ++r) {
        int row = rowBase + ty * 8 + r;
        if (row >= n) continue;
        float4 v = make_float4(acc[r][0], acc[r][1], acc[r][2], acc[r][3]);
        if (gcol < 128)
            *(float4*)&g_mapped[(size_t)row * D_OUT + gcol] = v;
        else
            *(float4*)&g_y[(size_t)row * 512 + (gcol - 128)] = v;
    }
}

// ---------------------------------------------------------------------------
// K3: scores s1/s2 = tanh(dot(y, xn)) — one warp per node
// ---------------------------------------------------------------------------
__global__ __launch_bounds__(256) void scores_kernel(const float* __restrict__ x, int n) {
    int wid  = (blockIdx.x * blockDim.x + threadIdx.x) >> 5;
    int lane = threadIdx.x & 31;
    if (wid >= n) return;
    float d1 = 0.f, d2 = 0.f;
    const float* xr = x + (size_t)wid * D_IN;
    const float* yr = g_y + (size_t)wid * 512;
    #pragma unroll
    for (int t = 0; t < 8; ++t) {
        int j = lane + 32 * t;
        float xv = (xr[j] - g_mean[j]) * g_rstd[j];
        d1 = fmaf(xv, yr[j],       d1);
        d2 = fmaf(xv, yr[j + 256], d2);
    }
    #pragma unroll
    for (int off = 16; off > 0; off >>= 1) {
        d1 += __shfl_xor_sync(0xffffffffu, d1, off);
        d2 += __shfl_xor_sync(0xffffffffu, d2, off);
    }
    if (lane == 0) {
        g_s1[wid] = tanhf(d1);
        g_s2[wid] = tanhf(d2);
    }
}

// ---------------------------------------------------------------------------
// K4: edge softmax + SpMM — one warp per row (rows sorted -> binary search)
// ---------------------------------------------------------------------------
__device__ __forceinline__ int lower_bound_i(const int* __restrict__ a, int len, int v) {
    int lo = 0, hi = len;
    while (lo < hi) {
        int mid = (lo + hi) >> 1;
        if (a[mid] < v) lo = mid + 1; else hi = mid;
    }
    return lo;
}

__global__ __launch_bounds__(256) void spmm_softmax(
    const float* __restrict__ edge_vals,
    const int*   __restrict__ rows,
    const int*   __restrict__ cols,
    float* __restrict__ out,
    int n, int e)
{
    int row  = (blockIdx.x * blockDim.x + threadIdx.x) >> 5;
    int lane = threadIdx.x & 31;
    if (row >= n) return;

    int lo = lower_bound_i(rows, e, row);
    int hi = lower_bound_i(rows, e, row + 1);

    const float4* mp = (const float4*)g_mapped;   // 32 float4 per node row
    float4 acc = make_float4(0.f, 0.f, 0.f, 0.f);

    if (hi > lo) {
        float s1i = g_s1[row];

        // pass A: row max of leaky-relu'd edge values
        float m = -INFINITY;
        for (int ee = lo + lane; ee < hi; ee += 32) {
            float ev = edge_vals[ee] * (s1i + g_s2[cols[ee]]);
            ev = ev > 0.f ? ev : LEAKY * ev;
            m = fmaxf(m, ev);
        }
        #pragma unroll
        for (int off = 16; off > 0; off >>= 1)
            m = fmaxf(m, __shfl_xor_sync(0xffffffffu, m, off));

        // pass B: denom
        float s = 0.f;
        for (int ee = lo + lane; ee < hi; ee += 32) {
            float ev = edge_vals[ee] * (s1i + g_s2[cols[ee]]);
            ev = ev > 0.f ? ev : LEAKY * ev;
            s += expf(ev - m);
        }
        #pragma unroll
        for (int off = 16; off > 0; off >>= 1)
            s += __shfl_xor_sync(0xffffffffu, s, off);
        float inv = 1.f / s;

        // pass C: weighted gather-accumulate; exp computed once/edge, shfl'd
        for (int base = lo; base < hi; base += 32) {
            int ee = base + lane;
            float wgt = 0.f;
            int   col = 0;
            if (ee < hi) {
                col = cols[ee];
                float ev = edge_vals[ee] * (s1i + g_s2[col]);
                ev = ev > 0.f ? ev : LEAKY * ev;
                wgt = expf(ev - m) * inv;
            }
            int cnt = min(32, hi - base);
            for (int j = 0; j < cnt; ++j) {
                float wj = __shfl_sync(0xffffffffu, wgt, j);
                int   cj = __shfl_sync(0xffffffffu, col, j);
                float4 mv = mp[(size_t)cj * 32 + lane];
                acc.x = fmaf(wj, mv.x, acc.x);
                acc.y = fmaf(wj, mv.y, acc.y);
                acc.z = fmaf(wj, mv.z, acc.z);
                acc.w = fmaf(wj, mv.w, acc.w);
            }
        }
    }
    ((float4*)out)[(size_t)row * 32 + lane] = acc;   // zeros for empty rows
}

// ---------------------------------------------------------------------------
extern "C" void kernel_launch(void* const* d_in, const int* in_sizes, int n_in,
                              void* d_out, int out_size) {
    const float* x   = (const float*)d_in[0];
    const float* w   = (const float*)d_in[1];
    const float* w1  = (const float*)d_in[2];
    const float* w2  = (const float*)d_in[3];
    const float* ev  = (const float*)d_in[4];
    const int*   rws = (const int*)d_in[5];
    const int*   cls = (const int*)d_in[6];
    float* out = (float*)d_out;

    int n = in_sizes[0] / D_IN;
    int e = in_sizes[4];
    if (n > NMAX) n = NMAX;

    bn_partial<<<NB_BN, 256>>>(x, n);
    bn_finalize<<<1, 256>>>(n, NB_BN);

    dim3 g2(640 / 64, (n + 127) / 128);
    gemm_fused<<<g2, 256>>>(x, w, w1, w2, n);

    scores_kernel<<<(n + 7) / 8, 256>>>(x, n);

    spmm_softmax<<<(n + 7) / 8, 256>>>(ev, rws, cls, out, n, e);
}

// round 2
// speedup vs baseline: 1.0448x; 1.0448x over previous
#include <cuda_runtime.h>
#include <cuda_bf16.h>
#include <math.h>

// ---------------------------------------------------------------------------
// AliNetGraphAttentionLayer: BN -> 3 fused GEMMs (packed f32x2 FMA, fused
// score partial-dots in epilogue) -> tanh finalize -> one-pass online edge
// softmax + SpMM.
// N=100000, D_IN=256, D_OUT=128, E=1600000 (rows sorted).
// ---------------------------------------------------------------------------

#define D_IN   256
#define D_OUT  128
#define NMAX   100096
#define EPS    1e-3f
#define LEAKY  0.2f
#define NB_BN  400

// ---- scratch --------------------------------------------------------------
__device__ float g_psum[NB_BN * D_IN];
__device__ float g_psq [NB_BN * D_IN];
__device__ float g_mean[D_IN];
__device__ float g_rstd[D_IN];
__device__ float g_s1[NMAX];
__device__ float g_s2[NMAX];
__device__ float g_part[(size_t)NMAX * 8];        // per-stripe partial dots
__device__ float g_mapped[(size_t)NMAX * D_OUT];  // xn @ w  [N,128]

// ---- packed f32x2 helpers -------------------------------------------------
#define FMA_F32X2(d, a, b, c) \
    asm("fma.rn.f32x2 %0, %1, %2, %3;" : "=l"(d) : "l"(a), "l"(b), "l"(c))
#define DUP_F32X2(out, f) \
    asm("mov.b64 %0, {%1, %1};" : "=l"(out) : "r"(__float_as_uint(f)))

__device__ __forceinline__ float f32x2_lo(unsigned long long v) {
    return __uint_as_float((unsigned)(v & 0xffffffffull));
}
__device__ __forceinline__ float f32x2_hi(unsigned long long v) {
    return __uint_as_float((unsigned)(v >> 32));
}

// ---------------------------------------------------------------------------
// K1a/K1b: BN stats
// ---------------------------------------------------------------------------
__global__ __launch_bounds__(256) void bn_partial(const float* __restrict__ x, int n) {
    int col = threadIdx.x;
    int per = (n + gridDim.x - 1) / gridDim.x;
    int r0 = blockIdx.x * per;
    int r1 = min(n, r0 + per);
    float s = 0.f, q = 0.f;
    for (int r = r0; r < r1; ++r) {
        float v = x[(size_t)r * D_IN + col];
        s += v;
        q += v * v;
    }
    g_psum[blockIdx.x * D_IN + col] = s;
    g_psq [blockIdx.x * D_IN + col] = q;
}

__global__ __launch_bounds__(256) void bn_finalize(int n, int nb) {
    int col = threadIdx.x;
    float s = 0.f, q = 0.f;
    for (int b = 0; b < nb; ++b) {
        s += g_psum[b * D_IN + col];
        q += g_psq [b * D_IN + col];
    }
    float mean = s / (float)n;
    float var  = q / (float)n - mean * mean;
    g_mean[col] = mean;
    g_rstd[col] = rsqrtf(var + EPS);
}

// ---------------------------------------------------------------------------
// K2: fused BN + GEMM  C[N,640] = xn @ [w | w1 | w2]
//     BM=128, BN=64, BK=32, 256 threads, 8x4 per-thread tile, f32x2 FMAs.
//     Stripes 0-1 (w)      -> g_mapped
//     Stripes 2-9 (w1/w2)  -> partial dot(y, xn) -> g_part (no y array!)
// ---------------------------------------------------------------------------
__global__ __launch_bounds__(256) void gemm_fused(
    const float* __restrict__ x,
    const float* __restrict__ w,
    const float* __restrict__ w1,
    const float* __restrict__ w2,
    int n)
{
    __shared__ float As[32][132];   // [k][m], padded
    __shared__ float Bs[32][68];    // [k][c], padded

    const int tid = threadIdx.x;
    const int tx  = tid & 15;       // col group (4 cols)
    const int ty  = tid >> 4;       // row group (8 rows)

    const int colBase = blockIdx.x * 64;
    const int rowBase = blockIdx.y * 128;

    const float* Bsrc;
    int ldb, srcCol;
    if (colBase < 128)       { Bsrc = w;  ldb = 128; srcCol = colBase; }
    else if (colBase < 384)  { Bsrc = w1; ldb = 256; srcCol = colBase - 128; }
    else                     { Bsrc = w2; ldb = 256; srcCol = colBase - 384; }

    // acc2[p][c]: row pair (ty*8+2p, ty*8+2p+1) x col (tx*4+c), packed f32x2
    unsigned long long acc2[4][4];
    #pragma unroll
    for (int p = 0; p < 4; ++p)
        #pragma unroll
        for (int c = 0; c < 4; ++c) acc2[p][c] = 0ull;

    for (int kBase = 0; kBase < D_IN; kBase += 32) {
        // A tile: 128 rows x 32 k, BN applied, stored [k][m]
        {
            int k4 = (tid & 7) * 4;
            float4 mn = *(const float4*)&g_mean[kBase + k4];
            float4 rs = *(const float4*)&g_rstd[kBase + k4];
            #pragma unroll
            for (int p = 0; p < 4; ++p) {
                int rl = (tid >> 3) + p * 32;
                int row = rowBase + rl;
                float4 v;
                if (row < n) v = *(const float4*)&x[(size_t)row * D_IN + kBase + k4];
                else         v = make_float4(0.f, 0.f, 0.f, 0.f);
                As[k4 + 0][rl] = (v.x - mn.x) * rs.x;
                As[k4 + 1][rl] = (v.y - mn.y) * rs.y;
                As[k4 + 2][rl] = (v.z - mn.z) * rs.z;
                As[k4 + 3][rl] = (v.w - mn.w) * rs.w;
            }
        }
        // B tile: 32 k x 64 cols
        {
            int c4 = (tid & 15) * 4;
            #pragma unroll
            for (int p = 0; p < 2; ++p) {
                int kk = (tid >> 4) + p * 16;
                float4 v = *(const float4*)&Bsrc[(size_t)(kBase + kk) * ldb + srcCol + c4];
                Bs[kk][c4 + 0] = v.x;
                Bs[kk][c4 + 1] = v.y;
                Bs[kk][c4 + 2] = v.z;
                Bs[kk][c4 + 3] = v.w;
            }
        }
        __syncthreads();

        #pragma unroll 8
        for (int kk = 0; kk < 32; ++kk) {
            // row pairs: LDS.64 straight into packed operands
            const unsigned long long* arow =
                (const unsigned long long*)&As[kk][ty * 8];
            unsigned long long a2_0 = arow[0];
            unsigned long long a2_1 = arow[1];
            unsigned long long a2_2 = arow[2];
            unsigned long long a2_3 = arow[3];
            float4 b4 = *(const float4*)&Bs[kk][tx * 4];
            unsigned long long bd0, bd1, bd2, bd3;
            DUP_F32X2(bd0, b4.x);
            DUP_F32X2(bd1, b4.y);
            DUP_F32X2(bd2, b4.z);
            DUP_F32X2(bd3, b4.w);
            FMA_F32X2(acc2[0][0], a2_0, bd0, acc2[0][0]);
            FMA_F32X2(acc2[0][1], a2_0, bd1, acc2[0][1]);
            FMA_F32X2(acc2[0][2], a2_0, bd2, acc2[0][2]);
            FMA_F32X2(acc2[0][3], a2_0, bd3, acc2[0][3]);
            FMA_F32X2(acc2[1][0], a2_1, bd0, acc2[1][0]);
            FMA_F32X2(acc2[1][1], a2_1, bd1, acc2[1][1]);
            FMA_F32X2(acc2[1][2], a2_1, bd2, acc2[1][2]);
            FMA_F32X2(acc2[1][3], a2_1, bd3, acc2[1][3]);
            FMA_F32X2(acc2[2][0], a2_2, bd0, acc2[2][0]);
            FMA_F32X2(acc2[2][1], a2_2, bd1, acc2[2][1]);
            FMA_F32X2(acc2[2][2], a2_2, bd2, acc2[2][2]);
            FMA_F32X2(acc2[2][3], a2_2, bd3, acc2[2][3]);
            FMA_F32X2(acc2[3][0], a2_3, bd0, acc2[3][0]);
            FMA_F32X2(acc2[3][1], a2_3, bd1, acc2[3][1]);
            FMA_F32X2(acc2[3][2], a2_3, bd2, acc2[3][2]);
            FMA_F32X2(acc2[3][3], a2_3, bd3, acc2[3][3]);
        }
        __syncthreads();
    }

    const int gcol = colBase + tx * 4;

    if (colBase < 128) {
        // mapped output
        #pragma unroll
        for (int p = 0; p < 4; ++p) {
            #pragma unroll
            for (int h = 0; h < 2; ++h) {
                int row = rowBase + ty * 8 + p * 2 + h;
                if (row >= n) continue;
                float4 v;
                v.x = h ? f32x2_hi(acc2[p][0]) : f32x2_lo(acc2[p][0]);
                v.y = h ? f32x2_hi(acc2[p][1]) : f32x2_lo(acc2[p][1]);
                v.z = h ? f32x2_hi(acc2[p][2]) : f32x2_lo(acc2[p][2]);
                v.w = h ? f32x2_hi(acc2[p][3]) : f32x2_lo(acc2[p][3]);
                *(float4*)&g_mapped[(size_t)row * D_OUT + gcol] = v;
            }
        }
    } else {
        // partial dot(y_row, xn_row) for this 64-col stripe
        int sidx = (colBase - 128) >> 6;        // 0..7
        int jc = srcCol + tx * 4;
        float4 mn = *(const float4*)&g_mean[jc];
        float4 rs = *(const float4*)&g_rstd[jc];
        #pragma unroll
        for (int p = 0; p < 4; ++p) {
            #pragma unroll
            for (int h = 0; h < 2; ++h) {
                int row = rowBase + ty * 8 + p * 2 + h;
                float d = 0.f;
                if (row < n) {
                    float4 xv = *(const float4*)&x[(size_t)row * D_IN + jc];
                    float y0 = h ? f32x2_hi(acc2[p][0]) : f32x2_lo(acc2[p][0]);
                    float y1 = h ? f32x2_hi(acc2[p][1]) : f32x2_lo(acc2[p][1]);
                    float y2 = h ? f32x2_hi(acc2[p][2]) : f32x2_lo(acc2[p][2]);
                    float y3 = h ? f32x2_hi(acc2[p][3]) : f32x2_lo(acc2[p][3]);
                    d  = y0 * (xv.x - mn.x) * rs.x;
                    d += y1 * (xv.y - mn.y) * rs.y;
                    d += y2 * (xv.z - mn.z) * rs.z;
                    d += y3 * (xv.w - mn.w) * rs.w;
                }
                // reduce across the 16 lanes sharing this row
                #pragma unroll
                for (int off = 8; off > 0; off >>= 1)
                    d += __shfl_xor_sync(0xffffffffu, d, off);
                if (tx == 0 && row < n)
                    g_part[(size_t)row * 8 + sidx] = d;
            }
        }
    }
}

// ---------------------------------------------------------------------------
// K3: tanh finalize (tiny)
// ---------------------------------------------------------------------------
__global__ __launch_bounds__(256) void scores_finalize(int n) {
    int i = blockIdx.x * blockDim.x + threadIdx.x;
    if (i >= n) return;
    const float* p = &g_part[(size_t)i * 8];
    g_s1[i] = tanhf(p[0] + p[1] + p[2] + p[3]);
    g_s2[i] = tanhf(p[4] + p[5] + p[6] + p[7]);
}

// ---------------------------------------------------------------------------
// K4: one-pass online edge softmax + SpMM — one warp per row
// ---------------------------------------------------------------------------
__device__ __forceinline__ int lower_bound_i(const int* __restrict__ a, int len, int v) {
    int lo = 0, hi = len;
    while (lo < hi) {
        int mid = (lo + hi) >> 1;
        if (a[mid] < v) lo = mid + 1; else hi = mid;
    }
    return lo;
}

__global__ __launch_bounds__(256) void spmm_softmax(
    const float* __restrict__ edge_vals,
    const int*   __restrict__ rows,
    const int*   __restrict__ cols,
    float* __restrict__ out,
    int n, int e)
{
    int row  = (blockIdx.x * blockDim.x + threadIdx.x) >> 5;
    int lane = threadIdx.x & 31;
    if (row >= n) return;

    int lo = lower_bound_i(rows, e, row);
    int hi = lower_bound_i(rows, e, row + 1);

    const float4* mp = (const float4*)g_mapped;
    float4 acc = make_float4(0.f, 0.f, 0.f, 0.f);

    if (hi > lo) {
        float s1i = g_s1[row];
        float m = -INFINITY;
        float s = 0.f;

        for (int base = lo; base < hi; base += 32) {
            int ee = base + lane;
            bool valid = ee < hi;
            float evv = -INFINITY;
            int   col = 0;
            if (valid) {
                col = cols[ee];
                float t = edge_vals[ee] * (s1i + g_s2[col]);
                evv = t > 0.f ? t : LEAKY * t;
            }
            // chunk max
            float cm = evv;
            #pragma unroll
            for (int off = 16; off > 0; off >>= 1)
                cm = fmaxf(cm, __shfl_xor_sync(0xffffffffu, cm, off));
            float nm = fmaxf(m, cm);
            float scale = (m == -INFINITY) ? 0.f : expf(m - nm);

            float p = valid ? expf(evv - nm) : 0.f;
            float ps = p;
            #pragma unroll
            for (int off = 16; off > 0; off >>= 1)
                ps += __shfl_xor_sync(0xffffffffu, ps, off);
            s = s * scale + ps;
            acc.x *= scale; acc.y *= scale; acc.z *= scale; acc.w *= scale;

            int cnt = min(32, hi - base);
            for (int j = 0; j < cnt; ++j) {
                float wj = __shfl_sync(0xffffffffu, p, j);
                int   cj = __shfl_sync(0xffffffffu, col, j);
                float4 mv = mp[(size_t)cj * 32 + lane];
                acc.x = fmaf(wj, mv.x, acc.x);
                acc.y = fmaf(wj, mv.y, acc.y);
                acc.z = fmaf(wj, mv.z, acc.z);
                acc.w = fmaf(wj, mv.w, acc.w);
            }
            m = nm;
        }
        float inv = 1.f / s;
        acc.x *= inv; acc.y *= inv; acc.z *= inv; acc.w *= inv;
    }
    ((float4*)out)[(size_t)row * 32 + lane] = acc;
}

// ---------------------------------------------------------------------------
extern "C" void kernel_launch(void* const* d_in, const int* in_sizes, int n_in,
                              void* d_out, int out_size) {
    const float* x   = (const float*)d_in[0];
    const float* w   = (const float*)d_in[1];
    const float* w1  = (const float*)d_in[2];
    const float* w2  = (const float*)d_in[3];
    const float* ev  = (const float*)d_in[4];
    const int*   rws = (const int*)d_in[5];
    const int*   cls = (const int*)d_in[6];
    float* out = (float*)d_out;

    int n = in_sizes[0] / D_IN;
    int e = in_sizes[4];
    if (n > NMAX) n = NMAX;

    bn_partial<<<NB_BN, 256>>>(x, n);
    bn_finalize<<<1, 256>>>(n, NB_BN);

    dim3 g2(640 / 64, (n + 127) / 128);
    gemm_fused<<<g2, 256>>>(x, w, w1, w2, n);

    scores_finalize<<<(n + 255) / 256, 256>>>(n);

    spmm_softmax<<<(n + 7) / 8, 256>>>(ev, rws, cls, out, n, e);
}

// round 4
// speedup vs baseline: 1.4992x; 1.4349x over previous
#include <cuda_runtime.h>
#include <cuda_bf16.h>
#include <math.h>
#include <stdint.h>

// ---------------------------------------------------------------------------
// AliNetGraphAttentionLayer on GB300 (baseline-PTX path: ldmatrix + mma.sync,
// since the harness compiles PTX at sm_103 without the 'a' feature set):
//   BN -> split-bf16 HMMA GEMM (hi*hi + lo*hi + hi*lo, fp32 accum)
//   -> fused score partial-dots from mma accumulators -> tanh
//   -> one-pass online edge softmax + SpMM.
// N=100000, D_IN=256, D_OUT=128, E=1600000 (rows sorted).
// ---------------------------------------------------------------------------

#define D_IN   256
#define NMAX   100096            // 782 * 128
#define EPS    1e-3f
#define LEAKY  0.2f
#define NB_BN  400
#define WCOLS  640               // w(128) | w1(256) | w2(256)

// ---- scratch --------------------------------------------------------------
__device__ float g_psum[NB_BN * D_IN];
__device__ float g_psq [NB_BN * D_IN];
__device__ float g_mean[D_IN];
__device__ float g_rstd[D_IN];
__device__ float g_s1[NMAX];
__device__ float g_s2[NMAX];
__device__ float g_part[(size_t)NMAX * 16];
__device__ float g_mapped[(size_t)NMAX * 128];
__device__ __nv_bfloat16 g_x_hi[(size_t)NMAX * D_IN];
__device__ __nv_bfloat16 g_x_lo[(size_t)NMAX * D_IN];
__device__ __nv_bfloat16 g_wc_hi[(size_t)WCOLS * D_IN];   // [ncol][k]
__device__ __nv_bfloat16 g_wc_lo[(size_t)WCOLS * D_IN];

// ---- warp mma helpers -----------------------------------------------------
__device__ __forceinline__ uint32_t smem_u32(const void* p) {
    uint32_t a;
    asm("{ .reg .u64 t; cvta.to.shared.u64 t, %1; cvt.u32.u64 %0, t; }"
        : "=r"(a) : "l"(p));
    return a;
}
__device__ __forceinline__ void ldsm4(uint32_t r[4], uint32_t addr) {
    asm volatile("ldmatrix.sync.aligned.m8n8.x4.shared.b16 {%0,%1,%2,%3}, [%4];"
                 : "=r"(r[0]), "=r"(r[1]), "=r"(r[2]), "=r"(r[3]) : "r"(addr));
}
__device__ __forceinline__ void mma16816(float d[4], const uint32_t a[4],
                                         uint32_t b0, uint32_t b1) {
    asm volatile(
        "mma.sync.aligned.m16n8k16.row.col.f32.bf16.bf16.f32 "
        "{%0,%1,%2,%3}, {%4,%5,%6,%7}, {%8,%9}, {%0,%1,%2,%3};"
        : "+f"(d[0]), "+f"(d[1]), "+f"(d[2]), "+f"(d[3])
        : "r"(a[0]), "r"(a[1]), "r"(a[2]), "r"(a[3]), "r"(b0), "r"(b1));
}

// ---------------------------------------------------------------------------
// BN stats
// ---------------------------------------------------------------------------
__global__ __launch_bounds__(256) void bn_partial(const float* __restrict__ x, int n) {
    int col = threadIdx.x;
    int per = (n + gridDim.x - 1) / gridDim.x;
    int r0 = blockIdx.x * per;
    int r1 = min(n, r0 + per);
    float s = 0.f, q = 0.f;
    for (int r = r0; r < r1; ++r) {
        float v = x[(size_t)r * D_IN + col];
        s += v;
        q += v * v;
    }
    g_psum[blockIdx.x * D_IN + col] = s;
    g_psq [blockIdx.x * D_IN + col] = q;
}

__global__ __launch_bounds__(256) void bn_finalize(int n, int nb) {
    int col = threadIdx.x;
    float s = 0.f, q = 0.f;
    for (int b = 0; b < nb; ++b) {
        s += g_psum[b * D_IN + col];
        q += g_psq [b * D_IN + col];
    }
    float mean = s / (float)n;
    float var  = q / (float)n - mean * mean;
    g_mean[col] = mean;
    g_rstd[col] = rsqrtf(var + EPS);
}

// ---------------------------------------------------------------------------
// convert x -> xn split into (hi, lo) bf16; rows >= n zeroed
// ---------------------------------------------------------------------------
__global__ __launch_bounds__(256) void convert_x(const float* __restrict__ x, int n) {
    size_t i = (size_t)blockIdx.x * blockDim.x + threadIdx.x;   // float4 index
    if (i >= (size_t)NMAX * 64) return;
    int row = (int)(i >> 6);
    int c4  = ((int)i & 63) * 4;
    float4 v = make_float4(0.f, 0.f, 0.f, 0.f);
    if (row < n) v = *(const float4*)&x[(size_t)row * D_IN + c4];
    float4 mn = *(const float4*)&g_mean[c4];
    float4 rs = *(const float4*)&g_rstd[c4];
    float xn[4];
    xn[0] = (v.x - mn.x) * rs.x;
    xn[1] = (v.y - mn.y) * rs.y;
    xn[2] = (v.z - mn.z) * rs.z;
    xn[3] = (v.w - mn.w) * rs.w;
    if (row >= n) { xn[0] = xn[1] = xn[2] = xn[3] = 0.f; }
    ushort hi[4], lo[4];
    #pragma unroll
    for (int j = 0; j < 4; ++j) {
        __nv_bfloat16 h = __float2bfloat16(xn[j]);
        __nv_bfloat16 l = __float2bfloat16(xn[j] - __bfloat162float(h));
        hi[j] = __bfloat16_as_ushort(h);
        lo[j] = __bfloat16_as_ushort(l);
    }
    uint2 ph = make_uint2((uint32_t)hi[0] | ((uint32_t)hi[1] << 16),
                          (uint32_t)hi[2] | ((uint32_t)hi[3] << 16));
    uint2 pl = make_uint2((uint32_t)lo[0] | ((uint32_t)lo[1] << 16),
                          (uint32_t)lo[2] | ((uint32_t)lo[3] << 16));
    *(uint2*)&g_x_hi[i * 4] = ph;
    *(uint2*)&g_x_lo[i * 4] = pl;
}

// ---------------------------------------------------------------------------
// transposed combined weights Wc[ncol][k] split hi/lo
// ---------------------------------------------------------------------------
__global__ __launch_bounds__(256) void prep_w(
    const float* __restrict__ w,
    const float* __restrict__ w1,
    const float* __restrict__ w2)
{
    int idx = blockIdx.x * blockDim.x + threadIdx.x;   // 0 .. 640*256-1
    int nc = idx >> 8;
    int k  = idx & 255;
    float v;
    if (nc < 128)       v = w [(size_t)k * 128 + nc];
    else if (nc < 384)  v = w1[(size_t)k * 256 + (nc - 128)];
    else                v = w2[(size_t)k * 256 + (nc - 384)];
    __nv_bfloat16 h = __float2bfloat16(v);
    __nv_bfloat16 l = __float2bfloat16(v - __bfloat162float(h));
    g_wc_hi[idx] = h;
    g_wc_lo[idx] = l;
}

// ---------------------------------------------------------------------------
// mma.sync GEMM: CTA 128 rows x 64 cols, 8 warps (4 m x 2 n), warp 32x32.
// 3-product bf16 split. grid = (10 stripes, rowTiles).
// Stripes 0-1 -> g_mapped; stripes 2-9 -> score partial dots -> g_part.
// ---------------------------------------------------------------------------
#define LDK 40                  // padded smem row pitch (bf16 elems) = 80 B

__global__ __launch_bounds__(256) void gemm_mma(int n) {
    __shared__ __align__(16) __nv_bfloat16 sAhi[128 * LDK];
    __shared__ __align__(16) __nv_bfloat16 sAlo[128 * LDK];
    __shared__ __align__(16) __nv_bfloat16 sBhi[64 * LDK];
    __shared__ __align__(16) __nv_bfloat16 sBlo[64 * LDK];

    const int tid  = threadIdx.x;
    const int wid  = tid >> 5;
    const int lane = tid & 31;
    const int warpM = wid >> 1;          // 0..3
    const int warpN = wid & 1;           // 0..1
    const int stripe  = blockIdx.x;      // 0..9
    const int rowBase = blockIdx.y * 128;

    const uint32_t aHiB = smem_u32(sAhi);
    const uint32_t aLoB = smem_u32(sAlo);
    const uint32_t bHiB = smem_u32(sBhi);
    const uint32_t bLoB = smem_u32(sBlo);

    // ldmatrix per-lane address components
    const uint32_t aRow  = ((lane >> 3) & 1) * 8 + (lane & 7);  // within m16
    const uint32_t aKoff = (lane >> 4) * 8;                     // elements
    const uint32_t bRow  = (lane >> 4) * 8 + (lane & 7);        // within n16 pair
    const uint32_t bKoff = ((lane >> 3) & 1) * 8;

    float acc[2][4][4];
    #pragma unroll
    for (int mt = 0; mt < 2; ++mt)
        #pragma unroll
        for (int nt = 0; nt < 4; ++nt)
            #pragma unroll
            for (int q = 0; q < 4; ++q) acc[mt][nt][q] = 0.f;

    for (int c = 0; c < 8; ++c) {
        const int kc0 = c * 32;
        // ---- load A tiles: 128 rows x 32 k (hi & lo) ----
        #pragma unroll
        for (int t = 0; t < 2; ++t) {
            int idx = t * 256 + tid;           // 0..511
            int r = idx >> 2, v = idx & 3;
            size_t gi = (size_t)(rowBase + r) * D_IN + kc0 + v * 8;
            uint32_t so = (uint32_t)(r * (LDK * 2) + v * 16);
            *(uint4*)((char*)sAhi + so) = *(const uint4*)&g_x_hi[gi];
            *(uint4*)((char*)sAlo + so) = *(const uint4*)&g_x_lo[gi];
        }
        // ---- load B tiles: 64 rows x 32 k (hi & lo) ----
        {
            int r = tid >> 2, v = tid & 3;
            size_t gi = (size_t)(stripe * 64 + r) * D_IN + kc0 + v * 8;
            uint32_t so = (uint32_t)(r * (LDK * 2) + v * 16);
            *(uint4*)((char*)sBhi + so) = *(const uint4*)&g_wc_hi[gi];
            *(uint4*)((char*)sBlo + so) = *(const uint4*)&g_wc_lo[gi];
        }
        __syncthreads();

        #pragma unroll
        for (int k16 = 0; k16 < 2; ++k16) {
            uint32_t ahi[2][4], alo[2][4];
            #pragma unroll
            for (int mt = 0; mt < 2; ++mt) {
                uint32_t off = (uint32_t)((warpM * 32 + mt * 16 + aRow) * (LDK * 2)
                                          + (k16 * 16 + aKoff) * 2);
                ldsm4(ahi[mt], aHiB + off);
                ldsm4(alo[mt], aLoB + off);
            }
            uint32_t bhi[2][4], blo[2][4];
            #pragma unroll
            for (int pr = 0; pr < 2; ++pr) {
                uint32_t off = (uint32_t)((warpN * 32 + pr * 16 + bRow) * (LDK * 2)
                                          + (k16 * 16 + bKoff) * 2);
                ldsm4(bhi[pr], bHiB + off);
                ldsm4(blo[pr], bLoB + off);
            }
            #pragma unroll
            for (int mt = 0; mt < 2; ++mt) {
                #pragma unroll
                for (int nt = 0; nt < 4; ++nt) {
                    int pr = nt >> 1, hf = nt & 1;
                    mma16816(acc[mt][nt], ahi[mt], bhi[pr][2 * hf], bhi[pr][2 * hf + 1]);
                    mma16816(acc[mt][nt], alo[mt], bhi[pr][2 * hf], bhi[pr][2 * hf + 1]);
                    mma16816(acc[mt][nt], ahi[mt], blo[pr][2 * hf], blo[pr][2 * hf + 1]);
                }
            }
        }
        __syncthreads();
    }

    // ---- epilogue ----
    const int gid = lane >> 2;       // row within m16 groups
    const int tc  = lane & 3;        // col pair

    if (stripe < 2) {
        #pragma unroll
        for (int mt = 0; mt < 2; ++mt) {
            int r0 = rowBase + warpM * 32 + mt * 16 + gid;
            #pragma unroll
            for (int nt = 0; nt < 4; ++nt) {
                int gcol = stripe * 64 + warpN * 32 + nt * 8 + 2 * tc;
                if (r0 < n)
                    *(float2*)&g_mapped[(size_t)r0 * 128 + gcol] =
                        make_float2(acc[mt][nt][0], acc[mt][nt][1]);
                if (r0 + 8 < n)
                    *(float2*)&g_mapped[(size_t)(r0 + 8) * 128 + gcol] =
                        make_float2(acc[mt][nt][2], acc[mt][nt][3]);
            }
        }
    } else {
        const int xoff = (stripe < 6) ? (stripe * 64 - 128) : (stripe * 64 - 384);
        float ds[2][2];
        ds[0][0] = ds[0][1] = ds[1][0] = ds[1][1] = 0.f;
        #pragma unroll
        for (int mt = 0; mt < 2; ++mt) {
            #pragma unroll
            for (int h = 0; h < 2; ++h) {
                int row = rowBase + warpM * 32 + mt * 16 + gid + 8 * h;
                const size_t rb = (size_t)row * D_IN;
                float d = 0.f;
                #pragma unroll
                for (int nt = 0; nt < 4; ++nt) {
                    int xcol = xoff + warpN * 32 + nt * 8 + 2 * tc;
                    __nv_bfloat162 h2 = *(const __nv_bfloat162*)&g_x_hi[rb + xcol];
                    __nv_bfloat162 l2 = *(const __nv_bfloat162*)&g_x_lo[rb + xcol];
                    float x0 = __bfloat162float(h2.x) + __bfloat162float(l2.x);
                    float x1 = __bfloat162float(h2.y) + __bfloat162float(l2.y);
                    d = fmaf(acc[mt][nt][2 * h + 0], x0, d);
                    d = fmaf(acc[mt][nt][2 * h + 1], x1, d);
                }
                ds[mt][h] = d;
            }
        }
        #pragma unroll
        for (int mt = 0; mt < 2; ++mt)
            #pragma unroll
            for (int h = 0; h < 2; ++h) {
                float d = ds[mt][h];
                d += __shfl_xor_sync(0xffffffffu, d, 1);
                d += __shfl_xor_sync(0xffffffffu, d, 2);
                ds[mt][h] = d;
            }
        if (tc == 0) {
            int slot = (stripe - 2) * 2 + warpN;
            #pragma unroll
            for (int mt = 0; mt < 2; ++mt)
                #pragma unroll
                for (int h = 0; h < 2; ++h) {
                    int row = rowBase + warpM * 32 + mt * 16 + gid + 8 * h;
                    g_part[(size_t)row * 16 + slot] = ds[mt][h];
                }
        }
    }
}

// ---------------------------------------------------------------------------
// tanh finalize
// ---------------------------------------------------------------------------
__global__ __launch_bounds__(256) void scores_finalize(int n) {
    int i = blockIdx.x * blockDim.x + threadIdx.x;
    if (i >= n) return;
    const float4* p = (const float4*)&g_part[(size_t)i * 16];
    float4 a = p[0], b = p[1], c = p[2], d = p[3];
    g_s1[i] = tanhf(a.x + a.y + a.z + a.w + b.x + b.y + b.z + b.w);
    g_s2[i] = tanhf(c.x + c.y + c.z + c.w + d.x + d.y + d.z + d.w);
}

// ---------------------------------------------------------------------------
// one-pass online edge softmax + SpMM — one warp per row
// ---------------------------------------------------------------------------
__device__ __forceinline__ int lower_bound_i(const int* __restrict__ a, int len, int v) {
    int lo = 0, hi = len;
    while (lo < hi) {
        int mid = (lo + hi) >> 1;
        if (a[mid] < v) lo = mid + 1; else hi = mid;
    }
    return lo;
}

__global__ __launch_bounds__(256) void spmm_softmax(
    const float* __restrict__ edge_vals,
    const int*   __restrict__ rows,
    const int*   __restrict__ cols,
    float* __restrict__ out,
    int n, int e)
{
    int row  = (blockIdx.x * blockDim.x + threadIdx.x) >> 5;
    int lane = threadIdx.x & 31;
    if (row >= n) return;

    int lo = lower_bound_i(rows, e, row);
    int hi = lower_bound_i(rows, e, row + 1);

    const float4* mp = (const float4*)g_mapped;
    float4 acc = make_float4(0.f, 0.f, 0.f, 0.f);

    if (hi > lo) {
        float s1i = g_s1[row];
        float m = -INFINITY;
        float s = 0.f;

        for (int base = lo; base < hi; base += 32) {
            int ee = base + lane;
            bool valid = ee < hi;
            float evv = -INFINITY;
            int   col = 0;
            if (valid) {
                col = cols[ee];
                float t = edge_vals[ee] * (s1i + g_s2[col]);
                evv = t > 0.f ? t : LEAKY * t;
            }
            float cm = evv;
            #pragma unroll
            for (int off = 16; off > 0; off >>= 1)
                cm = fmaxf(cm, __shfl_xor_sync(0xffffffffu, cm, off));
            float nm = fmaxf(m, cm);
            float scale = (m == -INFINITY) ? 0.f : expf(m - nm);

            float p = valid ? expf(evv - nm) : 0.f;
            float ps = p;
            #pragma unroll
            for (int off = 16; off > 0; off >>= 1)
                ps += __shfl_xor_sync(0xffffffffu, ps, off);
            s = s * scale + ps;
            acc.x *= scale; acc.y *= scale; acc.z *= scale; acc.w *= scale;

            int cnt = min(32, hi - base);
            for (int j = 0; j < cnt; ++j) {
                float wj = __shfl_sync(0xffffffffu, p, j);
                int   cj = __shfl_sync(0xffffffffu, col, j);
                float4 mv = mp[(size_t)cj * 32 + lane];
                acc.x = fmaf(wj, mv.x, acc.x);
                acc.y = fmaf(wj, mv.y, acc.y);
                acc.z = fmaf(wj, mv.z, acc.z);
                acc.w = fmaf(wj, mv.w, acc.w);
            }
            m = nm;
        }
        float inv = 1.f / s;
        acc.x *= inv; acc.y *= inv; acc.z *= inv; acc.w *= inv;
    }
    ((float4*)out)[(size_t)row * 32 + lane] = acc;
}

// ---------------------------------------------------------------------------
extern "C" void kernel_launch(void* const* d_in, const int* in_sizes, int n_in,
                              void* d_out, int out_size) {
    const float* x   = (const float*)d_in[0];
    const float* w   = (const float*)d_in[1];
    const float* w1  = (const float*)d_in[2];
    const float* w2  = (const float*)d_in[3];
    const float* ev  = (const float*)d_in[4];
    const int*   rws = (const int*)d_in[5];
    const int*   cls = (const int*)d_in[6];
    float* out = (float*)d_out;

    int n = in_sizes[0] / D_IN;
    int e = in_sizes[4];
    if (n > NMAX) n = NMAX;
    int rowTiles = (n + 127) / 128;

    bn_partial<<<NB_BN, 256>>>(x, n);
    bn_finalize<<<1, 256>>>(n, NB_BN);
    convert_x<<<(int)(((size_t)NMAX * 64 + 255) / 256), 256>>>(x, n);
    prep_w<<<WCOLS, 256>>>(w, w1, w2);
    gemm_mma<<<dim3(10, rowTiles), 256>>>(n);
    scores_finalize<<<(n + 255) / 256, 256>>>(n);
    spmm_softmax<<<(n + 7) / 8, 256>>>(ev, rws, cls, out, n, e);
}